// round 1
// baseline (speedup 1.0000x reference)
#include <cuda_runtime.h>
#include <math.h>

#define NTOK 32768
#define CCH  128
#define CF   512
#define NHEADS 8
#define HD   16
#define EPSF 1e-5f

// ---------------- scratch (device globals; no allocation allowed) ----------------
__device__ float g_q[NTOK*CCH];
__device__ float g_k[NTOK*CCH];
__device__ float g_v[NTOK*CCH];
__device__ float g_attn[NTOK*CCH];
__device__ float g_y[NTOK*CCH];     // proj out
__device__ float g_t[NTOK*CCH];     // instnorm1 out
__device__ float g_h1[NTOK*CF];     // ffn1 out
__device__ float g_u[NTOK*CCH];     // ffn2 + residual
__device__ float g_part[256*256];   // partial reduction buffer
__device__ float g_stats[2*CCH];    // [c]=sum, [128+c]=sumsq

__device__ __forceinline__ float gelu_tanh(float x) {
    const float c0 = 0.7978845608028654f;   // sqrt(2/pi)
    float x3 = x*x*x;
    return 0.5f*x*(1.0f + tanhf(c0*(x + 0.044715f*x3)));
}

// ---------------- K1: qkv GEMM.  out[n][o] = sum_c x[c][n]*w[o][c] + b[o] ----------------
// x is [C][N] (k-major already). Tile: 128 tokens x 64 outputs, K-chunks of 16.
__global__ __launch_bounds__(256) void qkv_gemm(const float* __restrict__ x,
                                                const float* __restrict__ w,
                                                const float* __restrict__ b) {
    __shared__ float Xs[16][128];
    __shared__ float Ws[16][68];   // pad to 68 -> 16B-aligned rows, fewer conflicts
    const int n0 = blockIdx.x * 128;
    const int o0 = blockIdx.y * 64;
    const int tx = threadIdx.x;
    const int to = tx & 15;    // 16 groups over o (4 each)
    const int tn = tx >> 4;    // 16 groups over n (8 each)

    float acc[8][4];
#pragma unroll
    for (int i = 0; i < 8; i++)
#pragma unroll
        for (int j = 0; j < 4; j++) acc[i][j] = 0.f;

    for (int kb = 0; kb < 128; kb += 16) {
#pragma unroll
        for (int r = 0; r < 2; r++) {
            int i  = tx + r*256;
            int kk = i >> 5;
            int nn = (i & 31) << 2;
            *(float4*)&Xs[kk][nn] =
                *(const float4*)&x[(size_t)(kb+kk)*NTOK + n0 + nn];
        }
        {
            int oo = tx >> 2;
            int k4 = (tx & 3) << 2;
            float4 wv = *(const float4*)&w[(size_t)(o0+oo)*128 + kb + k4];
            Ws[k4+0][oo] = wv.x; Ws[k4+1][oo] = wv.y;
            Ws[k4+2][oo] = wv.z; Ws[k4+3][oo] = wv.w;
        }
        __syncthreads();
#pragma unroll
        for (int k = 0; k < 16; k++) {
            float4 a0 = *(const float4*)&Xs[k][tn*8];
            float4 a1 = *(const float4*)&Xs[k][tn*8+4];
            float4 bb = *(const float4*)&Ws[k][to*4];
            float a[8] = {a0.x,a0.y,a0.z,a0.w,a1.x,a1.y,a1.z,a1.w};
            float bv[4] = {bb.x,bb.y,bb.z,bb.w};
#pragma unroll
            for (int i = 0; i < 8; i++)
#pragma unroll
                for (int j = 0; j < 4; j++) acc[i][j] += a[i]*bv[j];
        }
        __syncthreads();
    }
    // scatter into q/k/v as [n][128] each
    const int obase = o0 + to*4;
    float* dst = (obase < 128) ? g_q : (obase < 256) ? g_k : g_v;
    const int oc = obase & 127;
    float4 bias4;
    bias4.x = b[obase+0]; bias4.y = b[obase+1];
    bias4.z = b[obase+2]; bias4.w = b[obase+3];
#pragma unroll
    for (int i = 0; i < 8; i++) {
        int n = n0 + tn*8 + i;
        float4 v4;
        v4.x = acc[i][0] + bias4.x;
        v4.y = acc[i][1] + bias4.y;
        v4.z = acc[i][2] + bias4.z;
        v4.w = acc[i][3] + bias4.w;
        *(float4*)&dst[(size_t)n*128 + oc] = v4;
    }
}

// ---------------- K2: neighborhood attention. one block per token, one warp per head ----------------
__global__ __launch_bounds__(256) void attn_kernel(const float* __restrict__ rpb) {
    const int n = blockIdx.x;
    __shared__ int   s_nbr[27];
    __shared__ int   s_bidx[27];
    __shared__ float qs[NHEADS][HD];
    const int t = threadIdx.x;

    if (t < 27) {
        int hh = n >> 10, ww = (n >> 5) & 31, zz = n & 31;
        int sh = min(max(hh-1, 0), 29);
        int sw = min(max(ww-1, 0), 29);
        int sz = min(max(zz-1, 0), 29);
        int jh = t/9, jw = (t/3)%3, jz = t%3;
        s_nbr[t]  = (sh+jh)*1024 + (sw+jw)*32 + (sz+jz);
        int rh = sh+jh-hh+2, rw = sw+jw-ww+2, rz = sz+jz-zz+2;
        s_bidx[t] = (rh*5 + rw)*5 + rz;
    }
    if (t < 128) qs[t >> 4][t & 15] = g_q[(size_t)n*128 + t] * 0.25f; // * hd^-0.5
    __syncthreads();

    const int h = t >> 5, lane = t & 31;
    float score = -1e30f;
    if (lane < 27) {
        int nb = s_nbr[lane];
        const float4* kp = (const float4*)&g_k[(size_t)nb*128 + h*16];
        float s = 0.f;
#pragma unroll
        for (int q4 = 0; q4 < 4; q4++) {
            float4 kv = kp[q4];
            s += qs[h][q4*4+0]*kv.x + qs[h][q4*4+1]*kv.y
               + qs[h][q4*4+2]*kv.z + qs[h][q4*4+3]*kv.w;
        }
        score = s + rpb[h*125 + s_bidx[lane]];
    }
    float mx = score;
#pragma unroll
    for (int off = 16; off; off >>= 1) mx = fmaxf(mx, __shfl_xor_sync(0xffffffffu, mx, off));
    float p = (lane < 27) ? __expf(score - mx) : 0.f;
    float sum = p;
#pragma unroll
    for (int off = 16; off; off >>= 1) sum += __shfl_xor_sync(0xffffffffu, sum, off);
    float inv = 1.f / sum;

    float acc = 0.f;
#pragma unroll 1
    for (int j = 0; j < 27; j++) {
        float pj = __shfl_sync(0xffffffffu, p, j);
        int nb = s_nbr[j];
        if (lane < 16) acc += pj * g_v[(size_t)nb*128 + h*16 + lane];
    }
    if (lane < 16) g_attn[(size_t)n*128 + h*16 + lane] = acc * inv;
}

// ---------------- K3/K6/K7: NT GEMM.  out[n][o] = sum_k act[n][k]*w[o][k] (+bias,+epilogue) ----------------
// MODE 0: proj  (act=g_attn, K=128, O=128, out=g_y, +bias)
// MODE 1: ffn1  (act=g_t,    K=128, O=512, out=g_h1, gelu(+bias))
// MODE 2: ffn2  (act=g_h1,   K=512, O=128, out=g_u, +bias + residual g_t)
template<int MODE>
__global__ __launch_bounds__(256) void nt_gemm(const float* __restrict__ w,
                                               const float* __restrict__ bias) {
    const float* act = (MODE == 0) ? g_attn : (MODE == 1) ? g_t : g_h1;
    float* out       = (MODE == 0) ? g_y    : (MODE == 1) ? g_h1 : g_u;
    const int Kt = (MODE == 2) ? 512 : 128;
    const int Ot = (MODE == 1) ? 512 : 128;

    __shared__ float As[128][17];
    __shared__ float Ws[16][68];
    const int n0 = blockIdx.x * 128;
    const int o0 = blockIdx.y * 64;
    const int tx = threadIdx.x;
    const int to = tx & 15;
    const int tn = tx >> 4;

    float acc[8][4];
#pragma unroll
    for (int i = 0; i < 8; i++)
#pragma unroll
        for (int j = 0; j < 4; j++) acc[i][j] = 0.f;

    for (int kb = 0; kb < Kt; kb += 16) {
#pragma unroll
        for (int r = 0; r < 2; r++) {
            int i  = tx + r*256;
            int nn = i >> 2;
            int k4 = (i & 3) << 2;
            float4 av = *(const float4*)&act[(size_t)(n0+nn)*Kt + kb + k4];
            As[nn][k4+0] = av.x; As[nn][k4+1] = av.y;
            As[nn][k4+2] = av.z; As[nn][k4+3] = av.w;
        }
        {
            int oo = tx >> 2;
            int k4 = (tx & 3) << 2;
            float4 wv = *(const float4*)&w[(size_t)(o0+oo)*Kt + kb + k4];
            Ws[k4+0][oo] = wv.x; Ws[k4+1][oo] = wv.y;
            Ws[k4+2][oo] = wv.z; Ws[k4+3][oo] = wv.w;
        }
        __syncthreads();
#pragma unroll
        for (int k = 0; k < 16; k++) {
            float4 bb = *(const float4*)&Ws[k][to*4];
            float bv[4] = {bb.x,bb.y,bb.z,bb.w};
            float a[8];
#pragma unroll
            for (int i = 0; i < 8; i++) a[i] = As[tn*8+i][k];
#pragma unroll
            for (int i = 0; i < 8; i++)
#pragma unroll
                for (int j = 0; j < 4; j++) acc[i][j] += a[i]*bv[j];
        }
        __syncthreads();
    }

    const int ob = o0 + to*4;
    float4 bias4;
    bias4.x = bias[ob+0]; bias4.y = bias[ob+1];
    bias4.z = bias[ob+2]; bias4.w = bias[ob+3];
#pragma unroll
    for (int i = 0; i < 8; i++) {
        int n = n0 + tn*8 + i;
        float v0 = acc[i][0] + bias4.x;
        float v1 = acc[i][1] + bias4.y;
        float v2 = acc[i][2] + bias4.z;
        float v3 = acc[i][3] + bias4.w;
        if (MODE == 1) {
            v0 = gelu_tanh(v0); v1 = gelu_tanh(v1);
            v2 = gelu_tanh(v2); v3 = gelu_tanh(v3);
        } else if (MODE == 2) {
            const float4 r4 = *(const float4*)&g_t[(size_t)n*128 + ob];
            v0 += r4.x; v1 += r4.y; v2 += r4.z; v3 += r4.w;
        }
        float4 v4 = make_float4(v0, v1, v2, v3);
        *(float4*)&out[(size_t)n*Ot + ob] = v4;
    }
}

// ---------------- instance-norm reductions (deterministic, no atomics) ----------------
template<int MODE>  // 0: g_y, 1: g_u
__global__ __launch_bounds__(128) void reduce_partial() {
    const float* a = MODE ? g_u : g_y;
    const int c = threadIdx.x;
    const int b = blockIdx.x;              // 256 blocks x 128 tokens
    const float* p = a + (size_t)b*128*128;
    float s = 0.f, s2 = 0.f;
#pragma unroll 4
    for (int i = 0; i < 128; i++) {
        float v = p[i*128 + c];
        s += v; s2 += v*v;
    }
    g_part[b*256 + c]       = s;
    g_part[b*256 + 128 + c] = s2;
}

__global__ __launch_bounds__(256) void reduce_final() {
    const int t = threadIdx.x;             // t<128: sum, t>=128: sumsq
    float s = 0.f;
    for (int b = 0; b < 256; b++) s += g_part[b*256 + t];
    g_stats[t] = s;
}

__global__ __launch_bounds__(256) void norm_apply() {
    const int idx = blockIdx.x*256 + threadIdx.x;
    const int c = idx & 127;
    float m   = g_stats[c]       * (1.0f/NTOK);
    float var = g_stats[c+128]   * (1.0f/NTOK) - m*m;
    g_t[idx] = (g_y[idx] - m) * rsqrtf(var + EPSF);
}

// final instnorm + transpose to [C][N] output layout
__global__ __launch_bounds__(256) void norm_transpose(float* __restrict__ out) {
    __shared__ float tile[32][33];
    const int n0 = blockIdx.x*32, c0 = blockIdx.y*32;
    const int txx = threadIdx.x & 31, tyy = threadIdx.x >> 5;
    const int c = c0 + txx;
    float m   = g_stats[c]     * (1.0f/NTOK);
    float var = g_stats[c+128] * (1.0f/NTOK) - m*m;
    float rs  = rsqrtf(var + EPSF);
#pragma unroll
    for (int r = 0; r < 32; r += 8) {
        tile[tyy+r][txx] = (g_u[(size_t)(n0+tyy+r)*128 + c] - m) * rs;
    }
    __syncthreads();
#pragma unroll
    for (int r = 0; r < 32; r += 8) {
        out[(size_t)(c0+tyy+r)*NTOK + n0 + txx] = tile[txx][tyy+r];
    }
}

// ---------------- launch ----------------
extern "C" void kernel_launch(void* const* d_in, const int* in_sizes, int n_in,
                              void* d_out, int out_size) {
    const float* x      = (const float*)d_in[0];
    const float* w_qkv  = (const float*)d_in[1];
    const float* b_qkv  = (const float*)d_in[2];
    const float* rpb    = (const float*)d_in[3];
    const float* w_proj = (const float*)d_in[4];
    const float* b_proj = (const float*)d_in[5];
    const float* w_ffn1 = (const float*)d_in[6];
    const float* b_ffn1 = (const float*)d_in[7];
    const float* w_ffn2 = (const float*)d_in[8];
    const float* b_ffn2 = (const float*)d_in[9];
    float* out = (float*)d_out;

    qkv_gemm<<<dim3(NTOK/128, 3*CCH/64), 256>>>(x, w_qkv, b_qkv);
    attn_kernel<<<NTOK, 256>>>(rpb);
    nt_gemm<0><<<dim3(NTOK/128, CCH/64), 256>>>(w_proj, b_proj);
    reduce_partial<0><<<256, 128>>>();
    reduce_final<<<1, 256>>>();
    norm_apply<<<NTOK*CCH/256, 256>>>();
    nt_gemm<1><<<dim3(NTOK/128, CF/64), 256>>>(w_ffn1, b_ffn1);
    nt_gemm<2><<<dim3(NTOK/128, CCH/64), 256>>>(w_ffn2, b_ffn2);
    reduce_partial<1><<<256, 128>>>();
    reduce_final<<<1, 256>>>();
    norm_transpose<<<dim3(NTOK/32, CCH/32), 256>>>(out);
}